// round 15
// baseline (speedup 1.0000x reference)
#include <cuda_runtime.h>
#include <cstdint>

#define MAX_NODES 50000
__device__ float g_xw[(size_t)MAX_NODES * 128];   // x @ W[64:192] + b (fp32)
__device__ int   g_cnt[MAX_NODES + 4];            // histogram -> offsets
__device__ int4  g_esd[800064];                   // {edge, src, dst, 0} sorted by dst

// ---------------- helpers ----------------
__device__ __forceinline__ void red_add_v4(float* p, float a, float b, float c, float d) {
    asm volatile("red.global.add.v4.f32 [%0], {%1,%2,%3,%4};"
                 :: "l"(p), "f"(a), "f"(b), "f"(c), "f"(d) : "memory");
}
__device__ __forceinline__ uint32_t tf32r(float f) {
    uint32_t r; asm("cvt.rna.tf32.f32 %0, %1;" : "=r"(r) : "f"(f)); return r;
}
__device__ __forceinline__ uint32_t smem_u32(const void* p) {
    uint32_t a;
    asm("{ .reg .u64 t; cvta.to.shared.u64 t, %1; cvt.u32.u64 %0, t; }" : "=r"(a) : "l"(p));
    return a;
}
__device__ __forceinline__ void cp_async16(uint32_t dst, const void* src) {
    asm volatile("cp.async.cg.shared.global [%0], [%1], 16;" :: "r"(dst), "l"(src));
}
__device__ __forceinline__ void mma_tf32(float& c0, float& c1, float& c2, float& c3,
                                         uint32_t a0, uint32_t a1, uint32_t a2, uint32_t a3,
                                         uint32_t b0, uint32_t b1) {
    asm volatile("mma.sync.aligned.m16n8k8.row.col.f32.tf32.tf32.f32 "
                 "{%0,%1,%2,%3}, {%4,%5,%6,%7}, {%8,%9}, {%0,%1,%2,%3};"
                 : "+f"(c0), "+f"(c1), "+f"(c2), "+f"(c3)
                 : "r"(a0), "r"(a1), "r"(a2), "r"(a3), "r"(b0), "r"(b1));
}
__device__ __forceinline__ float4 ldg_v4(const float* p) {
    float4 v;
    asm volatile("ld.global.nc.v4.f32 {%0,%1,%2,%3}, [%4];"
                 : "=f"(v.x), "=f"(v.y), "=f"(v.z), "=f"(v.w) : "l"(p));
    return v;
}
__device__ __forceinline__ int colperm(int n) {
    int q = n & 15;
    return (q < 8) ? (n & ~15) + 4 * (q >> 1) + (q & 1)
                   : (n & ~15) + 4 * ((q - 8) >> 1) + 2 + (q & 1);
}

// ---------------------------------------------------------------------------
// Sort chain: zero -> histogram -> scan -> scatter (counting sort by dst)
// ---------------------------------------------------------------------------
__global__ void zero_cnt_kernel(int n) {
    int i = blockIdx.x * 256 + threadIdx.x;
    if (i < n) g_cnt[i] = 0;
}

__global__ void hist_kernel(const int* __restrict__ eidx, int E, int N) {
    for (int i = blockIdx.x * blockDim.x + threadIdx.x; i < E;
         i += gridDim.x * blockDim.x) {
        int d = eidx[(size_t)E + i];
        if ((unsigned)d < (unsigned)N) atomicAdd(&g_cnt[d + 1], 1);
    }
}

__global__ void scan_kernel(int n) {   // inclusive scan of g_cnt[0..n)
    __shared__ int wsum[32];
    __shared__ int sbase;
    int tid = threadIdx.x, lane = tid & 31, wid = tid >> 5;
    if (tid == 0) sbase = 0;
    __syncthreads();
    for (int c0 = 0; c0 < n; c0 += 1024) {
        int i = c0 + tid;
        int x = (i < n) ? g_cnt[i] : 0;
#pragma unroll
        for (int off = 1; off < 32; off <<= 1) {
            int t = __shfl_up_sync(0xffffffffu, x, off);
            if (lane >= off) x += t;
        }
        if (lane == 31) wsum[wid] = x;
        __syncthreads();
        if (wid == 0) {
            int y = wsum[lane];
#pragma unroll
            for (int off = 1; off < 32; off <<= 1) {
                int t = __shfl_up_sync(0xffffffffu, y, off);
                if (lane >= off) y += t;
            }
            wsum[lane] = y;
        }
        __syncthreads();
        int incl = x + (wid > 0 ? wsum[wid - 1] : 0);
        int b = sbase;
        if (i < n) g_cnt[i] = b + incl;
        __syncthreads();
        if (tid == 0) sbase = b + wsum[31];
        __syncthreads();
    }
}

__global__ void scatter_kernel(const int* __restrict__ eidx, int E, int N) {
    for (int i = blockIdx.x * blockDim.x + threadIdx.x; i < E;
         i += gridDim.x * blockDim.x) {
        int s = eidx[i];
        int d = eidx[(size_t)E + i];
        if ((unsigned)d < (unsigned)N) {
            int pos = atomicAdd(&g_cnt[d], 1);
            g_esd[pos] = make_int4(i, s, d, 0);
        }
    }
}

// ---------------------------------------------------------------------------
// Kernel A (fused): blocks [0,NB_ZERO) zero `out`; the rest run the node GEMM
// xW = x @ W[64:192] + b on mma.sync tf32 (K=128 = 2 phases of 64).
// ---------------------------------------------------------------------------
#define NB_ZERO  128
#define NA_OFF   65536
#define NBIAS_OFF 98304
#define NODE_SMEM (NBIAS_OFF + 512)

__global__ __launch_bounds__(256, 2)
void node_fused_kernel(const float* __restrict__ x,
                       const float* __restrict__ W,   // [192][128]
                       const float* __restrict__ b,
                       float* __restrict__ out, int out_n,
                       int N, int ntiles) {
    const int tid = threadIdx.x;

    if (blockIdx.x < NB_ZERO) {               // zero the output buffer
        float4 z = make_float4(0.f, 0.f, 0.f, 0.f);
        int total4 = out_n >> 2;
        for (int i = blockIdx.x * 256 + tid; i < total4; i += NB_ZERO * 256)
            ((float4*)out)[i] = z;
        return;
    }

    extern __shared__ char smem[];
    const uint32_t sb = smem_u32(smem);
    uint2* B_s   = (uint2*)smem;
    float* bias_s = (float*)(smem + NBIAS_OFF);

    const int wid  = tid >> 5, lane = tid & 31;
    const int g    = lane >> 2, t = lane & 3;
    const int wbase = wid * 16;
    const int tile = blockIdx.x - NB_ZERO;
    if (tile >= ntiles) return;
    const int n0 = tile * 128;

#pragma unroll
    for (int it = 0; it < 32; it++) {
        int i = tid + it * 256;
        int c = i & 3, n = (i >> 2) & 127, ks = i >> 9;
        int l = colperm(n);
        int k0 = 64 + ks * 8 + c;
        B_s[i] = make_uint2(tf32r(W[(size_t)k0 * 128 + l]),
                            tf32r(W[(size_t)(k0 + 4) * 128 + l]));
    }
    if (tid < 128) bias_s[tid] = b[tid];

    float acc[16][4];
#pragma unroll
    for (int nt = 0; nt < 16; nt++)
#pragma unroll
        for (int j = 0; j < 4; j++) acc[nt][j] = 0.0f;

    for (int h = 0; h < 2; h++) {
#pragma unroll
        for (int it = 0; it < 8; it++) {
            int i = tid + it * 256;
            int e = i >> 4, q = i & 15;
            int n = n0 + e; if (n > N - 1) n = N - 1;
            uint32_t dst = sb + NA_OFF + e * 256 + ((q ^ (e & 7)) << 4);
            cp_async16(dst, x + (size_t)n * 128 + h * 64 + q * 4);
        }
        asm volatile("cp.async.commit_group;" ::: "memory");
        asm volatile("cp.async.wait_group 0;" ::: "memory");
        __syncthreads();

        const float* Abuf = (const float*)(smem + NA_OFF);
        const float* ar0 = Abuf + (wbase + g) * 64;
        const float* ar1 = Abuf + (wbase + 8 + g) * 64;
#pragma unroll
        for (int ks = 0; ks < 8; ks++) {
            int c0 = (((2 * ks)     ^ g) << 2) + t;
            int c1 = (((2 * ks + 1) ^ g) << 2) + t;
            uint32_t a0 = tf32r(ar0[c0]);
            uint32_t a1 = tf32r(ar1[c0]);
            uint32_t a2 = tf32r(ar0[c1]);
            uint32_t a3 = tf32r(ar1[c1]);
            const uint2* brow = B_s + (h * 8 + ks) * 512 + g * 4 + t;
#pragma unroll
            for (int nt = 0; nt < 16; nt++) {
                uint2 bv = brow[nt * 32];
                mma_tf32(acc[nt][0], acc[nt][1], acc[nt][2], acc[nt][3],
                         a0, a1, a2, a3, bv.x, bv.y);
            }
        }
        if (h == 0) __syncthreads();
    }

#pragma unroll
    for (int rs = 0; rs < 2; rs++) {
        int m = wbase + g + 8 * rs;
        int n = n0 + m;
        if (n >= N) continue;
        float* p = &g_xw[(size_t)n * 128];
#pragma unroll
        for (int q = 0; q < 8; q++) {
            int lc = q * 16 + 4 * t;
            float4 bv = *(const float4*)&bias_s[lc];
            float4 v = make_float4(acc[2 * q    ][rs * 2    ] + bv.x,
                                   acc[2 * q    ][rs * 2 + 1] + bv.y,
                                   acc[2 * q + 1][rs * 2    ] + bv.z,
                                   acc[2 * q + 1][rs * 2 + 1] + bv.w);
            *(float4*)&p[lc] = v;
        }
    }
}

// ---------------------------------------------------------------------------
// Kernel B: warp-PAIR edge pipeline over DST-SORTED edges (g_esd).
// Pair j shares one 16-edge tile + double-buffered A; warp h owns cols
// [64h,64h+64). Same-dst row pairs merged in registers before RED; sorted
// order makes RED lane-groups hit the same line (1 wavefront vs 8).
// smem: B @0 (32KB) | pair j: A bufs 2x4KB @ 32768 + j*8192
// ---------------------------------------------------------------------------
#define AW_OFF  32768
#define EDGE_SMEM (AW_OFF + 4 * 8192)   // 65536

__global__ __launch_bounds__(256, 2)
void edge_mma_kernel(const float* __restrict__ ea,   // [E][64]
                     const float* __restrict__ W,    // [192][128]
                     float* __restrict__ out,        // [N][128]
                     int E, int N, int ntiles) {
    extern __shared__ char smem[];
    const uint32_t sb = smem_u32(smem);
    uint2* B2 = (uint2*)smem;
    const uint4* B4 = (const uint4*)smem;

    const int tid  = threadIdx.x;
    const int wid  = tid >> 5, lane = tid & 31;
    const int g    = lane >> 2, t = lane & 3;
    const int tp   = g * 4 + t;
    const int j    = wid >> 1;        // pair id 0..3
    const int h    = wid & 1;         // column half
    const int barid = 1 + j;
    const unsigned Eu = (unsigned)E;

    // build B fragments from W rows [0,64), paired uint4 layout (4096 uint2)
    for (int i = tid; i < 4096; i += 256) {
        int c = i & 3, n = (i >> 2) & 127, ks = i >> 9;
        int l = colperm(n);
        int k0 = ks * 8 + c;
        uint2 v = make_uint2(tf32r(W[(size_t)k0 * 128 + l]),
                             tf32r(W[(size_t)(k0 + 4) * 128 + l]));
        int nt = n >> 3, gg = n & 7;
        int i2 = ks * 512 + (nt >> 1) * 64 + (gg * 4 + c) * 2 + (nt & 1);
        B2[i2] = v;
    }
    __syncthreads();

    const uint32_t a_base = sb + AW_OFF + j * 8192;
    const float*   a_ptr0 = (const float*)(smem + AW_OFF + j * 8192);

    // coalesced record load: lane m < 16 holds {edge,src,dst} for tile row m
    auto load_rec = [&](unsigned tile) -> int4 {
        int4 r = make_int4(0, 0, -1, 0);
        unsigned idx = tile * 16u + (unsigned)lane;
        if (lane < 16 && tile < (unsigned)ntiles && idx < Eu)
            r = g_esd[idx];
        if ((unsigned)r.x >= Eu) r.x = 0;   // defensive clamp for ea loads
        return r;
    };

    // cooperative pair issue from permuted edge ids (shfl from rec.x)
    auto issue = [&](int p2, int pvx) {
#pragma unroll
        for (int it = 0; it < 4; it++) {
            int i = h * 128 + lane + it * 32;   // 128 chunks per warp
            int e = i >> 4, qq = i & 15;
            int pe = __shfl_sync(0xffffffffu, pvx, e);
            cp_async16(a_base + p2 * 4096 + e * 256 + ((qq ^ (e & 7)) << 4),
                       ea + (size_t)pe * 64 + qq * 4);
        }
        asm volatile("cp.async.commit_group;" ::: "memory");
    };

    const unsigned stride = gridDim.x * 4;
    unsigned et = blockIdx.x * 4 + j;
    int p = 0;
    int4 rec_cur = load_rec(et);
    int4 rec_nxt = load_rec(et + stride);
    if (et < (unsigned)ntiles) issue(0, rec_cur.x);

    for (; et < (unsigned)ntiles; et += stride) {
        int s0 = __shfl_sync(0xffffffffu, rec_cur.y, g);
        int d0 = __shfl_sync(0xffffffffu, rec_cur.z, g);
        int s1 = __shfl_sync(0xffffffffu, rec_cur.y, g + 8);
        int d1 = __shfl_sync(0xffffffffu, rec_cur.z, g + 8);

        // (a) gather prefetch into regs: this warp's column half
        int ss0 = ((unsigned)s0 < (unsigned)N) ? s0 : 0;
        int ss1 = ((unsigned)s1 < (unsigned)N) ? s1 : 0;
        float4 gv0[4], gv1[4];
        {
            const float* gp0 = g_xw + (size_t)ss0 * 128 + h * 64 + 4 * t;
            const float* gp1 = g_xw + (size_t)ss1 * 128 + h * 64 + 4 * t;
#pragma unroll
            for (int q = 0; q < 4; q++) gv0[q] = ldg_v4(gp0 + q * 16);
#pragma unroll
            for (int q = 0; q < 4; q++) gv1[q] = ldg_v4(gp1 + q * 16);
        }

        // (b) bar A: partner finished reading buffer p^1
        asm volatile("bar.sync %0, 64;" :: "r"(barid) : "memory");

        unsigned next = et + stride;
        int4 rec_nn = make_int4(0, 0, -1, 0);
        if (next < (unsigned)ntiles) {
            issue(p ^ 1, rec_nxt.x);
            rec_nn = load_rec(next + stride);
            asm volatile("cp.async.wait_group 1;" ::: "memory");
        } else {
            asm volatile("cp.async.wait_group 0;" ::: "memory");
        }
        // (c) bar B: partner's writes to buffer p landed
        asm volatile("bar.sync %0, 64;" :: "r"(barid) : "memory");

        // (d) MMA from buffer p
        float acc[8][4];
#pragma unroll
        for (int nt = 0; nt < 8; nt++)
#pragma unroll
            for (int jj = 0; jj < 4; jj++) acc[nt][jj] = 0.0f;

        const float* Abuf = a_ptr0 + p * 1024;
        const float* ar0 = Abuf + g * 64;
        const float* ar1 = Abuf + (8 + g) * 64;
#pragma unroll
        for (int ks = 0; ks < 8; ks++) {
            int c0 = (((2 * ks)     ^ g) << 2) + t;
            int c1 = (((2 * ks + 1) ^ g) << 2) + t;
            uint32_t a0 = tf32r(ar0[c0]);
            uint32_t a1 = tf32r(ar1[c0]);
            uint32_t a2 = tf32r(ar0[c1]);
            uint32_t a3 = tf32r(ar1[c1]);
            const uint4* b4 = B4 + ks * 256 + h * 128 + tp;
#pragma unroll
            for (int pp = 0; pp < 4; pp++) {
                uint4 bw = b4[pp * 32];
                mma_tf32(acc[2 * pp    ][0], acc[2 * pp    ][1],
                         acc[2 * pp    ][2], acc[2 * pp    ][3],
                         a0, a1, a2, a3, bw.x, bw.y);
                mma_tf32(acc[2 * pp + 1][0], acc[2 * pp + 1][1],
                         acc[2 * pp + 1][2], acc[2 * pp + 1][3],
                         a0, a1, a2, a3, bw.z, bw.w);
            }
        }

        // (e) epilogue: ReLU + gather add; merge same-dst row pairs, RED
        unsigned ebase = et * 16u;
        bool ok0 = (ebase + g     < Eu) && ((unsigned)d0 < (unsigned)N);
        bool ok1 = (ebase + g + 8 < Eu) && ((unsigned)d1 < (unsigned)N);
        if (ok0 && ok1 && d0 == d1) {
            float* op = &out[(size_t)d0 * 128 + h * 64];
#pragma unroll
            for (int q = 0; q < 4; q++) {
                int lc = q * 16 + 4 * t;
                float4 ga = gv0[q], gb = gv1[q];
                float v0 = fmaxf(acc[2*q  ][0] + ga.x, 0.f) + fmaxf(acc[2*q  ][2] + gb.x, 0.f);
                float v1 = fmaxf(acc[2*q  ][1] + ga.y, 0.f) + fmaxf(acc[2*q  ][3] + gb.y, 0.f);
                float v2 = fmaxf(acc[2*q+1][0] + ga.z, 0.f) + fmaxf(acc[2*q+1][2] + gb.z, 0.f);
                float v3 = fmaxf(acc[2*q+1][1] + ga.w, 0.f) + fmaxf(acc[2*q+1][3] + gb.w, 0.f);
                red_add_v4(op + lc, v0, v1, v2, v3);
            }
        } else {
            if (ok0) {
                float* op = &out[(size_t)d0 * 128 + h * 64];
#pragma unroll
                for (int q = 0; q < 4; q++) {
                    int lc = q * 16 + 4 * t;
                    float4 ga = gv0[q];
                    red_add_v4(op + lc,
                               fmaxf(acc[2*q  ][0] + ga.x, 0.f),
                               fmaxf(acc[2*q  ][1] + ga.y, 0.f),
                               fmaxf(acc[2*q+1][0] + ga.z, 0.f),
                               fmaxf(acc[2*q+1][1] + ga.w, 0.f));
                }
            }
            if (ok1) {
                float* op = &out[(size_t)d1 * 128 + h * 64];
#pragma unroll
                for (int q = 0; q < 4; q++) {
                    int lc = q * 16 + 4 * t;
                    float4 gb = gv1[q];
                    red_add_v4(op + lc,
                               fmaxf(acc[2*q  ][2] + gb.x, 0.f),
                               fmaxf(acc[2*q  ][3] + gb.y, 0.f),
                               fmaxf(acc[2*q+1][2] + gb.z, 0.f),
                               fmaxf(acc[2*q+1][3] + gb.w, 0.f));
                }
            }
        }
        rec_cur = rec_nxt; rec_nxt = rec_nn;
        p ^= 1;
    }
}

extern "C" void kernel_launch(void* const* d_in, const int* in_sizes, int n_in,
                              void* d_out, int out_size) {
    const float* x    = (const float*)d_in[0];
    const int*   eidx = (const int*)d_in[1];   // int32 [2][E]
    const float* ea   = (const float*)d_in[2];
    const float* W    = (const float*)d_in[3];
    const float* b    = (const float*)d_in[4];
    float* out = (float*)d_out;

    const int N = in_sizes[0] / 128;   // 50000
    const int E = in_sizes[2] / 64;    // 800000
    const int ntilesN = (N + 127) / 128;
    const int ntilesE = (E + 15) / 16;

    cudaFuncSetAttribute(node_fused_kernel,
                         cudaFuncAttributeMaxDynamicSharedMemorySize, NODE_SMEM);
    cudaFuncSetAttribute(edge_mma_kernel,
                         cudaFuncAttributeMaxDynamicSharedMemorySize, EDGE_SMEM);

    // counting sort by dst
    zero_cnt_kernel<<<(N + 1 + 255) / 256, 256>>>(N + 1);
    hist_kernel<<<400, 256>>>(eidx, E, N);
    scan_kernel<<<1, 1024>>>(N + 1);
    scatter_kernel<<<400, 256>>>(eidx, E, N);

    node_fused_kernel<<<NB_ZERO + ntilesN, 256, NODE_SMEM>>>(x, W, b, out, out_size, N, ntilesN);

    edge_mma_kernel<<<296, 256, EDGE_SMEM>>>(ea, W, out, E, N, ntilesE);
}

// round 16
// speedup vs baseline: 1.3576x; 1.3576x over previous
#include <cuda_runtime.h>
#include <cuda_fp16.h>
#include <cstdint>

#define MAX_NODES 50000
__device__ __half2 g_xw[(size_t)MAX_NODES * 64];   // x @ W[64:192] + b (fp16)

// ---------------- helpers ----------------
__device__ __forceinline__ void red_add_v4(float* p, float a, float b, float c, float d) {
    asm volatile("red.global.add.v4.f32 [%0], {%1,%2,%3,%4};"
                 :: "l"(p), "f"(a), "f"(b), "f"(c), "f"(d) : "memory");
}
__device__ __forceinline__ uint32_t tf32r(float f) {
    uint32_t r; asm("cvt.rna.tf32.f32 %0, %1;" : "=r"(r) : "f"(f)); return r;
}
__device__ __forceinline__ uint32_t smem_u32(const void* p) {
    uint32_t a;
    asm("{ .reg .u64 t; cvta.to.shared.u64 t, %1; cvt.u32.u64 %0, t; }" : "=r"(a) : "l"(p));
    return a;
}
__device__ __forceinline__ void cp_async16(uint32_t dst, const void* src) {
    asm volatile("cp.async.cg.shared.global [%0], [%1], 16;" :: "r"(dst), "l"(src));
}
__device__ __forceinline__ void mma_tf32(float& c0, float& c1, float& c2, float& c3,
                                         uint32_t a0, uint32_t a1, uint32_t a2, uint32_t a3,
                                         uint32_t b0, uint32_t b1) {
    asm volatile("mma.sync.aligned.m16n8k8.row.col.f32.tf32.tf32.f32 "
                 "{%0,%1,%2,%3}, {%4,%5,%6,%7}, {%8,%9}, {%0,%1,%2,%3};"
                 : "+f"(c0), "+f"(c1), "+f"(c2), "+f"(c3)
                 : "r"(a0), "r"(a1), "r"(a2), "r"(a3), "r"(b0), "r"(b1));
}
__device__ __forceinline__ uint2 ldg_v2u(const void* p) {
    uint2 v;
    asm volatile("ld.global.nc.v2.u32 {%0,%1}, [%2];"
                 : "=r"(v.x), "=r"(v.y) : "l"(p));
    return v;
}
// unpack 4 fp16 (two half2) to float4
__device__ __forceinline__ float4 h4_to_f4(uint2 raw) {
    __half2 h0 = *(__half2*)&raw.x;
    __half2 h1 = *(__half2*)&raw.y;
    float2 lo = __half22float2(h0);
    float2 hi = __half22float2(h1);
    return make_float4(lo.x, lo.y, hi.x, hi.y);
}
// logical column for physical fragment column n (each thread's 4 cols contiguous)
__device__ __forceinline__ int colperm(int n) {
    int q = n & 15;
    return (q < 8) ? (n & ~15) + 4 * (q >> 1) + (q & 1)
                   : (n & ~15) + 4 * ((q - 8) >> 1) + 2 + (q & 1);
}

// ---------------------------------------------------------------------------
// Kernel A (fused): blocks [0,NB_ZERO) zero `out`; the rest run the node GEMM
// xW = x @ W[64:192] + b on mma.sync tf32 (K=128 = 2 phases of 64).
// Epilogue stores g_xw in fp16 (halves edge-kernel gather traffic).
// ---------------------------------------------------------------------------
#define NB_ZERO  128
#define NA_OFF   65536
#define NBIAS_OFF 98304
#define NODE_SMEM (NBIAS_OFF + 512)

__global__ __launch_bounds__(256, 2)
void node_fused_kernel(const float* __restrict__ x,
                       const float* __restrict__ W,   // [192][128]
                       const float* __restrict__ b,
                       float* __restrict__ out, int out_n,
                       int N, int ntiles) {
    const int tid = threadIdx.x;

    if (blockIdx.x < NB_ZERO) {               // zero the output buffer
        float4 z = make_float4(0.f, 0.f, 0.f, 0.f);
        int total4 = out_n >> 2;
        for (int i = blockIdx.x * 256 + tid; i < total4; i += NB_ZERO * 256)
            ((float4*)out)[i] = z;
        return;
    }

    extern __shared__ char smem[];
    const uint32_t sb = smem_u32(smem);
    uint2* B_s   = (uint2*)smem;
    float* bias_s = (float*)(smem + NBIAS_OFF);

    const int wid  = tid >> 5, lane = tid & 31;
    const int g    = lane >> 2, t = lane & 3;
    const int wbase = wid * 16;
    const int tile = blockIdx.x - NB_ZERO;
    if (tile >= ntiles) return;
    const int n0 = tile * 128;

    // build B fragments from W rows [64,192): 8192 uint2 entries
#pragma unroll
    for (int it = 0; it < 32; it++) {
        int i = tid + it * 256;
        int c = i & 3, n = (i >> 2) & 127, ks = i >> 9;
        int l = colperm(n);
        int k0 = 64 + ks * 8 + c;
        B_s[i] = make_uint2(tf32r(W[(size_t)k0 * 128 + l]),
                            tf32r(W[(size_t)(k0 + 4) * 128 + l]));
    }
    if (tid < 128) bias_s[tid] = b[tid];

    float acc[16][4];
#pragma unroll
    for (int nt = 0; nt < 16; nt++)
#pragma unroll
        for (int j = 0; j < 4; j++) acc[nt][j] = 0.0f;

    for (int h = 0; h < 2; h++) {
#pragma unroll
        for (int it = 0; it < 8; it++) {
            int i = tid + it * 256;
            int e = i >> 4, q = i & 15;
            int n = n0 + e; if (n > N - 1) n = N - 1;
            uint32_t dst = sb + NA_OFF + e * 256 + ((q ^ (e & 7)) << 4);
            cp_async16(dst, x + (size_t)n * 128 + h * 64 + q * 4);
        }
        asm volatile("cp.async.commit_group;" ::: "memory");
        asm volatile("cp.async.wait_group 0;" ::: "memory");
        __syncthreads();

        const float* Abuf = (const float*)(smem + NA_OFF);
        const float* ar0 = Abuf + (wbase + g) * 64;
        const float* ar1 = Abuf + (wbase + 8 + g) * 64;
#pragma unroll
        for (int ks = 0; ks < 8; ks++) {
            int c0 = (((2 * ks)     ^ g) << 2) + t;
            int c1 = (((2 * ks + 1) ^ g) << 2) + t;
            uint32_t a0 = tf32r(ar0[c0]);
            uint32_t a1 = tf32r(ar1[c0]);
            uint32_t a2 = tf32r(ar0[c1]);
            uint32_t a3 = tf32r(ar1[c1]);
            const uint2* brow = B_s + (h * 8 + ks) * 512 + g * 4 + t;
#pragma unroll
            for (int nt = 0; nt < 16; nt++) {
                uint2 bv = brow[nt * 32];
                mma_tf32(acc[nt][0], acc[nt][1], acc[nt][2], acc[nt][3],
                         a0, a1, a2, a3, bv.x, bv.y);
            }
        }
        if (h == 0) __syncthreads();   // A buffer reused for half 1
    }

    // epilogue: add bias, store fp16 rows of g_xw
#pragma unroll
    for (int rs = 0; rs < 2; rs++) {
        int m = wbase + g + 8 * rs;
        int n = n0 + m;
        if (n >= N) continue;
        __half2* p = &g_xw[(size_t)n * 64];
#pragma unroll
        for (int q = 0; q < 8; q++) {
            int lc = q * 16 + 4 * t;
            float4 bv = *(const float4*)&bias_s[lc];
            __half2 h0 = __floats2half2_rn(acc[2 * q    ][rs * 2    ] + bv.x,
                                           acc[2 * q    ][rs * 2 + 1] + bv.y);
            __half2 h1 = __floats2half2_rn(acc[2 * q + 1][rs * 2    ] + bv.z,
                                           acc[2 * q + 1][rs * 2 + 1] + bv.w);
            uint2 pk;
            pk.x = *(uint32_t*)&h0;
            pk.y = *(uint32_t*)&h1;
            *(uint2*)&p[q * 8 + 2 * t] = pk;    // half2 idx lc/2
        }
    }
}

// ---------------------------------------------------------------------------
// Kernel B: warp-PAIR edge pipeline (R11 structure), 256 threads, 2 CTA/SM.
// Pair j shares one 16-edge tile + double-buffered A; warp h = wid&1 owns
// cols [64h,64h+64). Gather of xW[src] is fp16 (1 line per edge per warp).
// smem: B @0 (32KB) | pair j: A bufs 2x4KB @ 32768 + j*8192
// ---------------------------------------------------------------------------
#define AW_OFF  32768
#define EDGE_SMEM (AW_OFF + 4 * 8192)   // 65536

__global__ __launch_bounds__(256, 2)
void edge_mma_kernel(const int* __restrict__ eidx,   // [2][E] int32
                     const float* __restrict__ ea,   // [E][64]
                     const float* __restrict__ W,    // [192][128]
                     float* __restrict__ out,        // [N][128]
                     int E, int N, int ntiles) {
    extern __shared__ char smem[];
    const uint32_t sb = smem_u32(smem);
    uint2* B2 = (uint2*)smem;
    const uint4* B4 = (const uint4*)smem;

    const int tid  = threadIdx.x;
    const int wid  = tid >> 5, lane = tid & 31;
    const int g    = lane >> 2, t = lane & 3;
    const int tp   = g * 4 + t;
    const int j    = wid >> 1;        // pair id 0..3
    const int h    = wid & 1;         // column half
    const int barid = 1 + j;
    const unsigned Eu = (unsigned)E, Em1 = Eu - 1;

    // build B fragments from W rows [0,64), paired uint4 layout (4096 uint2)
    for (int i = tid; i < 4096; i += 256) {
        int c = i & 3, n = (i >> 2) & 127, ks = i >> 9;
        int l = colperm(n);
        int k0 = ks * 8 + c;
        uint2 v = make_uint2(tf32r(W[(size_t)k0 * 128 + l]),
                             tf32r(W[(size_t)(k0 + 4) * 128 + l]));
        int nt = n >> 3, gg = n & 7;
        int i2 = ks * 512 + (nt >> 1) * 64 + (gg * 4 + c) * 2 + (nt & 1);
        B2[i2] = v;
    }
    __syncthreads();

    const uint32_t a_base = sb + AW_OFF + j * 8192;
    const float*   a_ptr0 = (const float*)(smem + AW_OFF + j * 8192);

    // cooperative pair issue: warp h loads edges [8h, 8h+8) of the tile
    auto issue = [&](unsigned et2, int p2) {
        unsigned ebase = et2 * 16u;
#pragma unroll
        for (int it = 0; it < 4; it++) {
            int i = h * 128 + lane + it * 32;   // 128 chunks per warp
            int e = i >> 4, q = i & 15;
            unsigned se = ebase + e; if (se > Em1) se = Em1;
            cp_async16(a_base + p2 * 4096 + e * 256 + ((q ^ (e & 7)) << 4),
                       ea + (size_t)se * 64 + q * 4);
        }
        asm volatile("cp.async.commit_group;" ::: "memory");
    };

    const unsigned stride = gridDim.x * 4;
    unsigned et = blockIdx.x * 4 + j;
    int p = 0;
    int s0 = -1, d0 = -1, s1 = -1, d1 = -1;
    if (et < (unsigned)ntiles) {
        issue(et, 0);
        unsigned ebase = et * 16u;
        if (ebase + g < Eu) {
            s0 = eidx[ebase + g];
            d0 = eidx[Eu + ebase + g];
        }
        if (ebase + g + 8 < Eu) {
            s1 = eidx[ebase + g + 8];
            d1 = eidx[Eu + ebase + g + 8];
        }
    }

    for (; et < (unsigned)ntiles; et += stride) {
        // (a) gather prefetch (fp16): this warp's column half = 128B/row
        int ss0 = ((unsigned)s0 < (unsigned)N) ? s0 : 0;
        int ss1 = ((unsigned)s1 < (unsigned)N) ? s1 : 0;
        uint2 gr0[4], gr1[4];
        {
            const __half2* gp0 = g_xw + (size_t)ss0 * 64 + h * 32 + 2 * t;
            const __half2* gp1 = g_xw + (size_t)ss1 * 64 + h * 32 + 2 * t;
#pragma unroll
            for (int q = 0; q < 4; q++) gr0[q] = ldg_v2u(gp0 + q * 8);
#pragma unroll
            for (int q = 0; q < 4; q++) gr1[q] = ldg_v2u(gp1 + q * 8);
        }

        // (b) bar A: partner finished reading buffer p^1 (prev iteration)
        asm volatile("bar.sync %0, 64;" :: "r"(barid) : "memory");

        unsigned next = et + stride;
        int ns0 = -1, nd0 = -1, ns1 = -1, nd1 = -1;
        if (next < (unsigned)ntiles) {
            issue(next, p ^ 1);
            unsigned nb = next * 16u;
            if (nb + g < Eu) {
                ns0 = eidx[nb + g];
                nd0 = eidx[Eu + nb + g];
            }
            if (nb + g + 8 < Eu) {
                ns1 = eidx[nb + g + 8];
                nd1 = eidx[Eu + nb + g + 8];
            }
            asm volatile("cp.async.wait_group 1;" ::: "memory");
        } else {
            asm volatile("cp.async.wait_group 0;" ::: "memory");
        }
        // (c) bar B: partner's writes to buffer p have landed too
        asm volatile("bar.sync %0, 64;" :: "r"(barid) : "memory");

        // (d) MMA from buffer p
        float acc[8][4];
#pragma unroll
        for (int nt = 0; nt < 8; nt++)
#pragma unroll
            for (int jj = 0; jj < 4; jj++) acc[nt][jj] = 0.0f;

        const float* Abuf = a_ptr0 + p * 1024;
        const float* ar0 = Abuf + g * 64;
        const float* ar1 = Abuf + (8 + g) * 64;
#pragma unroll
        for (int ks = 0; ks < 8; ks++) {
            int c0 = (((2 * ks)     ^ g) << 2) + t;
            int c1 = (((2 * ks + 1) ^ g) << 2) + t;
            uint32_t a0 = tf32r(ar0[c0]);
            uint32_t a1 = tf32r(ar1[c0]);
            uint32_t a2 = tf32r(ar0[c1]);
            uint32_t a3 = tf32r(ar1[c1]);
            const uint4* b4 = B4 + ks * 256 + h * 128 + tp;
#pragma unroll
            for (int pp = 0; pp < 4; pp++) {
                uint4 bw = b4[pp * 32];
                mma_tf32(acc[2 * pp    ][0], acc[2 * pp    ][1],
                         acc[2 * pp    ][2], acc[2 * pp    ][3],
                         a0, a1, a2, a3, bw.x, bw.y);
                mma_tf32(acc[2 * pp + 1][0], acc[2 * pp + 1][1],
                         acc[2 * pp + 1][2], acc[2 * pp + 1][3],
                         a0, a1, a2, a3, bw.z, bw.w);
            }
        }

        // (e) epilogue: ReLU(acc + gathered) -> vector atomic scatter
        unsigned ebase = et * 16u;
#pragma unroll
        for (int rs = 0; rs < 2; rs++) {
            int d = rs ? d1 : d0;
            int m = g + 8 * rs;
            if (ebase + m >= Eu || (unsigned)d >= (unsigned)N) continue;
            float* op = &out[(size_t)d * 128 + h * 64];
            uint2* grp = rs ? gr1 : gr0;
#pragma unroll
            for (int q = 0; q < 4; q++) {
                int lc = q * 16 + 4 * t;
                float4 gvv = h4_to_f4(grp[q]);
                float v0 = fmaxf(acc[2 * q    ][rs * 2    ] + gvv.x, 0.f);
                float v1 = fmaxf(acc[2 * q    ][rs * 2 + 1] + gvv.y, 0.f);
                float v2 = fmaxf(acc[2 * q + 1][rs * 2    ] + gvv.z, 0.f);
                float v3 = fmaxf(acc[2 * q + 1][rs * 2 + 1] + gvv.w, 0.f);
                red_add_v4(op + lc, v0, v1, v2, v3);
            }
        }
        s0 = ns0; d0 = nd0; s1 = ns1; d1 = nd1;
        p ^= 1;
    }
}

extern "C" void kernel_launch(void* const* d_in, const int* in_sizes, int n_in,
                              void* d_out, int out_size) {
    const float* x    = (const float*)d_in[0];
    const int*   eidx = (const int*)d_in[1];   // int32 [2][E]
    const float* ea   = (const float*)d_in[2];
    const float* W    = (const float*)d_in[3];
    const float* b    = (const float*)d_in[4];
    float* out = (float*)d_out;

    const int N = in_sizes[0] / 128;   // 50000
    const int E = in_sizes[2] / 64;    // 800000
    const int ntilesN = (N + 127) / 128;
    const int ntilesE = (E + 15) / 16; // 16-edge tiles

    cudaFuncSetAttribute(node_fused_kernel,
                         cudaFuncAttributeMaxDynamicSharedMemorySize, NODE_SMEM);
    cudaFuncSetAttribute(edge_mma_kernel,
                         cudaFuncAttributeMaxDynamicSharedMemorySize, EDGE_SMEM);

    node_fused_kernel<<<NB_ZERO + ntilesN, 256, NODE_SMEM>>>(x, W, b, out, out_size, N, ntilesN);

    edge_mma_kernel<<<296, 256, EDGE_SMEM>>>(eidx, ea, W, out, E, N, ntilesE);
}

// round 17
// speedup vs baseline: 1.4593x; 1.0750x over previous
#include <cuda_runtime.h>
#include <cuda_fp16.h>
#include <cstdint>

#define MAX_NODES 50000
// x @ W[64:192] + b, fp16, COLUMN-PERMUTED: element (n, h*64 + t*16 + q*4 + i)
// holds logical column h*64 + q*16 + 4t + i  (h=half, t=0..3, q=0..3, i=0..3)
__device__ __half g_xw[(size_t)MAX_NODES * 128];

// ---------------- helpers ----------------
__device__ __forceinline__ void red_add_v4(float* p, float a, float b, float c, float d) {
    asm volatile("red.global.add.v4.f32 [%0], {%1,%2,%3,%4};"
                 :: "l"(p), "f"(a), "f"(b), "f"(c), "f"(d) : "memory");
}
__device__ __forceinline__ uint32_t tf32r(float f) {
    uint32_t r; asm("cvt.rna.tf32.f32 %0, %1;" : "=r"(r) : "f"(f)); return r;
}
__device__ __forceinline__ uint32_t smem_u32(const void* p) {
    uint32_t a;
    asm("{ .reg .u64 t; cvta.to.shared.u64 t, %1; cvt.u32.u64 %0, t; }" : "=r"(a) : "l"(p));
    return a;
}
__device__ __forceinline__ void cp_async16(uint32_t dst, const void* src) {
    asm volatile("cp.async.cg.shared.global [%0], [%1], 16;" :: "r"(dst), "l"(src));
}
__device__ __forceinline__ void mma_tf32(float& c0, float& c1, float& c2, float& c3,
                                         uint32_t a0, uint32_t a1, uint32_t a2, uint32_t a3,
                                         uint32_t b0, uint32_t b1) {
    asm volatile("mma.sync.aligned.m16n8k8.row.col.f32.tf32.tf32.f32 "
                 "{%0,%1,%2,%3}, {%4,%5,%6,%7}, {%8,%9}, {%0,%1,%2,%3};"
                 : "+f"(c0), "+f"(c1), "+f"(c2), "+f"(c3)
                 : "r"(a0), "r"(a1), "r"(a2), "r"(a3), "r"(b0), "r"(b1));
}
__device__ __forceinline__ uint4 ldg_v4u(const void* p) {
    uint4 v;
    asm volatile("ld.global.nc.v4.u32 {%0,%1,%2,%3}, [%4];"
                 : "=r"(v.x), "=r"(v.y), "=r"(v.z), "=r"(v.w) : "l"(p));
    return v;
}
// unpack 4 fp16 (two packed half2 words) to float4
__device__ __forceinline__ float4 h4_to_f4(uint32_t r0, uint32_t r1) {
    __half2 h0 = *(__half2*)&r0;
    __half2 h1 = *(__half2*)&r1;
    float2 lo = __half22float2(h0);
    float2 hi = __half22float2(h1);
    return make_float4(lo.x, lo.y, hi.x, hi.y);
}
// logical column for physical fragment column n (each thread's 4 cols contiguous)
__device__ __forceinline__ int colperm(int n) {
    int q = n & 15;
    return (q < 8) ? (n & ~15) + 4 * (q >> 1) + (q & 1)
                   : (n & ~15) + 4 * ((q - 8) >> 1) + 2 + (q & 1);
}

// ---------------------------------------------------------------------------
// Kernel A (fused): blocks [0,NB_ZERO) zero `out`; the rest run the node GEMM
// xW = x @ W[64:192] + b on mma.sync tf32 (K=128 = 2 phases of 64).
// Epilogue stores g_xw fp16 in the gather-permuted layout.
// ---------------------------------------------------------------------------
#define NB_ZERO  128
#define NA_OFF   65536
#define NBIAS_OFF 98304
#define NODE_SMEM (NBIAS_OFF + 512)

__global__ __launch_bounds__(256, 2)
void node_fused_kernel(const float* __restrict__ x,
                       const float* __restrict__ W,   // [192][128]
                       const float* __restrict__ b,
                       float* __restrict__ out, int out_n,
                       int N, int ntiles) {
    const int tid = threadIdx.x;

    if (blockIdx.x < NB_ZERO) {               // zero the output buffer
        float4 z = make_float4(0.f, 0.f, 0.f, 0.f);
        int total4 = out_n >> 2;
        for (int i = blockIdx.x * 256 + tid; i < total4; i += NB_ZERO * 256)
            ((float4*)out)[i] = z;
        return;
    }

    extern __shared__ char smem[];
    const uint32_t sb = smem_u32(smem);
    uint2* B_s   = (uint2*)smem;
    float* bias_s = (float*)(smem + NBIAS_OFF);

    const int wid  = tid >> 5, lane = tid & 31;
    const int g    = lane >> 2, t = lane & 3;
    const int wbase = wid * 16;
    const int tile = blockIdx.x - NB_ZERO;
    if (tile >= ntiles) return;
    const int n0 = tile * 128;

    // build B fragments from W rows [64,192): 8192 uint2 entries
#pragma unroll
    for (int it = 0; it < 32; it++) {
        int i = tid + it * 256;
        int c = i & 3, n = (i >> 2) & 127, ks = i >> 9;
        int l = colperm(n);
        int k0 = 64 + ks * 8 + c;
        B_s[i] = make_uint2(tf32r(W[(size_t)k0 * 128 + l]),
                            tf32r(W[(size_t)(k0 + 4) * 128 + l]));
    }
    if (tid < 128) bias_s[tid] = b[tid];

    float acc[16][4];
#pragma unroll
    for (int nt = 0; nt < 16; nt++)
#pragma unroll
        for (int j = 0; j < 4; j++) acc[nt][j] = 0.0f;

    for (int h = 0; h < 2; h++) {
#pragma unroll
        for (int it = 0; it < 8; it++) {
            int i = tid + it * 256;
            int e = i >> 4, q = i & 15;
            int n = n0 + e; if (n > N - 1) n = N - 1;
            uint32_t dst = sb + NA_OFF + e * 256 + ((q ^ (e & 7)) << 4);
            cp_async16(dst, x + (size_t)n * 128 + h * 64 + q * 4);
        }
        asm volatile("cp.async.commit_group;" ::: "memory");
        asm volatile("cp.async.wait_group 0;" ::: "memory");
        __syncthreads();

        const float* Abuf = (const float*)(smem + NA_OFF);
        const float* ar0 = Abuf + (wbase + g) * 64;
        const float* ar1 = Abuf + (wbase + 8 + g) * 64;
#pragma unroll
        for (int ks = 0; ks < 8; ks++) {
            int c0 = (((2 * ks)     ^ g) << 2) + t;
            int c1 = (((2 * ks + 1) ^ g) << 2) + t;
            uint32_t a0 = tf32r(ar0[c0]);
            uint32_t a1 = tf32r(ar1[c0]);
            uint32_t a2 = tf32r(ar0[c1]);
            uint32_t a3 = tf32r(ar1[c1]);
            const uint2* brow = B_s + (h * 8 + ks) * 512 + g * 4 + t;
#pragma unroll
            for (int nt = 0; nt < 16; nt++) {
                uint2 bv = brow[nt * 32];
                mma_tf32(acc[nt][0], acc[nt][1], acc[nt][2], acc[nt][3],
                         a0, a1, a2, a3, bv.x, bv.y);
            }
        }
        if (h == 0) __syncthreads();   // A buffer reused for half 1
    }

    // epilogue: add bias, store fp16 g_xw in the PERMUTED layout:
    // logical col q*16+4t+{0..3}  ->  element (q>>2)*64 + t*16 + (q&3)*4 + {0..3}
#pragma unroll
    for (int rs = 0; rs < 2; rs++) {
        int m = wbase + g + 8 * rs;
        int n = n0 + m;
        if (n >= N) continue;
        __half* p = &g_xw[(size_t)n * 128];
#pragma unroll
        for (int q = 0; q < 8; q++) {
            int lc = q * 16 + 4 * t;               // logical col base
            float4 bv = *(const float4*)&bias_s[lc];
            __half2 h0 = __floats2half2_rn(acc[2 * q    ][rs * 2    ] + bv.x,
                                           acc[2 * q    ][rs * 2 + 1] + bv.y);
            __half2 h1 = __floats2half2_rn(acc[2 * q + 1][rs * 2    ] + bv.z,
                                           acc[2 * q + 1][rs * 2 + 1] + bv.w);
            uint2 pk;
            pk.x = *(uint32_t*)&h0;
            pk.y = *(uint32_t*)&h1;
            int off = (q >> 2) * 64 + t * 16 + (q & 3) * 4;   // permuted fp16 idx
            *(uint2*)&p[off] = pk;
        }
    }
}

// ---------------------------------------------------------------------------
// Kernel B: warp-PAIR edge pipeline (R11 structure), 256 threads, 2 CTA/SM.
// Pair j shares one 16-edge tile + double-buffered A; warp h = wid&1 owns
// cols [64h,64h+64). Gather of xW[src]: permuted fp16 layout makes each
// thread's 16 needed values 32 CONTIGUOUS bytes -> 2 ldg.128 per edge.
// smem: B @0 (32KB) | pair j: A bufs 2x4KB @ 32768 + j*8192
// ---------------------------------------------------------------------------
#define AW_OFF  32768
#define EDGE_SMEM (AW_OFF + 4 * 8192)   // 65536

__global__ __launch_bounds__(256, 2)
void edge_mma_kernel(const int* __restrict__ eidx,   // [2][E] int32
                     const float* __restrict__ ea,   // [E][64]
                     const float* __restrict__ W,    // [192][128]
                     float* __restrict__ out,        // [N][128]
                     int E, int N, int ntiles) {
    extern __shared__ char smem[];
    const uint32_t sb = smem_u32(smem);
    uint2* B2 = (uint2*)smem;
    const uint4* B4 = (const uint4*)smem;

    const int tid  = threadIdx.x;
    const int wid  = tid >> 5, lane = tid & 31;
    const int g    = lane >> 2, t = lane & 3;
    const int tp   = g * 4 + t;
    const int j    = wid >> 1;        // pair id 0..3
    const int h    = wid & 1;         // column half
    const int barid = 1 + j;
    const unsigned Eu = (unsigned)E, Em1 = Eu - 1;

    // build B fragments from W rows [0,64), paired uint4 layout (4096 uint2)
    for (int i = tid; i < 4096; i += 256) {
        int c = i & 3, n = (i >> 2) & 127, ks = i >> 9;
        int l = colperm(n);
        int k0 = ks * 8 + c;
        uint2 v = make_uint2(tf32r(W[(size_t)k0 * 128 + l]),
                             tf32r(W[(size_t)(k0 + 4) * 128 + l]));
        int nt = n >> 3, gg = n & 7;
        int i2 = ks * 512 + (nt >> 1) * 64 + (gg * 4 + c) * 2 + (nt & 1);
        B2[i2] = v;
    }
    __syncthreads();

    const uint32_t a_base = sb + AW_OFF + j * 8192;
    const float*   a_ptr0 = (const float*)(smem + AW_OFF + j * 8192);

    // cooperative pair issue: warp h loads edges [8h, 8h+8) of the tile
    auto issue = [&](unsigned et2, int p2) {
        unsigned ebase = et2 * 16u;
#pragma unroll
        for (int it = 0; it < 4; it++) {
            int i = h * 128 + lane + it * 32;   // 128 chunks per warp
            int e = i >> 4, q = i & 15;
            unsigned se = ebase + e; if (se > Em1) se = Em1;
            cp_async16(a_base + p2 * 4096 + e * 256 + ((q ^ (e & 7)) << 4),
                       ea + (size_t)se * 64 + q * 4);
        }
        asm volatile("cp.async.commit_group;" ::: "memory");
    };

    const unsigned stride = gridDim.x * 4;
    unsigned et = blockIdx.x * 4 + j;
    int p = 0;
    int s0 = -1, d0 = -1, s1 = -1, d1 = -1;
    if (et < (unsigned)ntiles) {
        issue(et, 0);
        unsigned ebase = et * 16u;
        if (ebase + g < Eu) {
            s0 = eidx[ebase + g];
            d0 = eidx[Eu + ebase + g];
        }
        if (ebase + g + 8 < Eu) {
            s1 = eidx[ebase + g + 8];
            d1 = eidx[Eu + ebase + g + 8];
        }
    }

    for (; et < (unsigned)ntiles; et += stride) {
        // (a) gather prefetch (fp16, permuted): 16 values = 32 contiguous B
        //     = 2 x ldg.128 per edge
        int ss0 = ((unsigned)s0 < (unsigned)N) ? s0 : 0;
        int ss1 = ((unsigned)s1 < (unsigned)N) ? s1 : 0;
        uint4 u00, u01, u10, u11;
        {
            const __half* gp0 = g_xw + (size_t)ss0 * 128 + h * 64 + t * 16;
            const __half* gp1 = g_xw + (size_t)ss1 * 128 + h * 64 + t * 16;
            u00 = ldg_v4u(gp0);          // q = 0,1
            u01 = ldg_v4u(gp0 + 8);      // q = 2,3
            u10 = ldg_v4u(gp1);
            u11 = ldg_v4u(gp1 + 8);
        }

        // (b) bar A: partner finished reading buffer p^1 (prev iteration)
        asm volatile("bar.sync %0, 64;" :: "r"(barid) : "memory");

        unsigned next = et + stride;
        int ns0 = -1, nd0 = -1, ns1 = -1, nd1 = -1;
        if (next < (unsigned)ntiles) {
            issue(next, p ^ 1);
            unsigned nb = next * 16u;
            if (nb + g < Eu) {
                ns0 = eidx[nb + g];
                nd0 = eidx[Eu + nb + g];
            }
            if (nb + g + 8 < Eu) {
                ns1 = eidx[nb + g + 8];
                nd1 = eidx[Eu + nb + g + 8];
            }
            asm volatile("cp.async.wait_group 1;" ::: "memory");
        } else {
            asm volatile("cp.async.wait_group 0;" ::: "memory");
        }
        // (c) bar B: partner's writes to buffer p have landed too
        asm volatile("bar.sync %0, 64;" :: "r"(barid) : "memory");

        // (d) MMA from buffer p
        float acc[8][4];
#pragma unroll
        for (int nt = 0; nt < 8; nt++)
#pragma unroll
            for (int jj = 0; jj < 4; jj++) acc[nt][jj] = 0.0f;

        const float* Abuf = a_ptr0 + p * 1024;
        const float* ar0 = Abuf + g * 64;
        const float* ar1 = Abuf + (8 + g) * 64;
#pragma unroll
        for (int ks = 0; ks < 8; ks++) {
            int c0 = (((2 * ks)     ^ g) << 2) + t;
            int c1 = (((2 * ks + 1) ^ g) << 2) + t;
            uint32_t a0 = tf32r(ar0[c0]);
            uint32_t a1 = tf32r(ar1[c0]);
            uint32_t a2 = tf32r(ar0[c1]);
            uint32_t a3 = tf32r(ar1[c1]);
            const uint4* b4 = B4 + ks * 256 + h * 128 + tp;
#pragma unroll
            for (int pp = 0; pp < 4; pp++) {
                uint4 bw = b4[pp * 32];
                mma_tf32(acc[2 * pp    ][0], acc[2 * pp    ][1],
                         acc[2 * pp    ][2], acc[2 * pp    ][3],
                         a0, a1, a2, a3, bw.x, bw.y);
                mma_tf32(acc[2 * pp + 1][0], acc[2 * pp + 1][1],
                         acc[2 * pp + 1][2], acc[2 * pp + 1][3],
                         a0, a1, a2, a3, bw.z, bw.w);
            }
        }

        // (e) epilogue: ReLU(acc + gathered) -> vector atomic scatter
        unsigned ebase = et * 16u;
#pragma unroll
        for (int rs = 0; rs < 2; rs++) {
            int d = rs ? d1 : d0;
            int m = g + 8 * rs;
            if (ebase + m >= Eu || (unsigned)d >= (unsigned)N) continue;
            float* op = &out[(size_t)d * 128 + h * 64];
            uint4 ua = rs ? u10 : u00;
            uint4 ub = rs ? u11 : u01;
#pragma unroll
            for (int q = 0; q < 4; q++) {
                int lc = q * 16 + 4 * t;
                uint32_t r0 = (q == 0) ? ua.x : (q == 1) ? ua.z : (q == 2) ? ub.x : ub.z;
                uint32_t r1 = (q == 0) ? ua.y : (q == 1) ? ua.w : (q == 2) ? ub.y : ub.w;
                float4 gvv = h4_to_f4(r0, r1);
                float v0 = fmaxf(acc[2 * q    ][rs * 2    ] + gvv.x, 0.f);
                float v1 = fmaxf(acc[2 * q    ][rs * 2 + 1] + gvv.y, 0.f);
                float v2 = fmaxf(acc[2 * q + 1][rs * 2    ] + gvv.z, 0.f);
                float v3 = fmaxf(acc[2 * q + 1][rs * 2 + 1] + gvv.w, 0.f);
                red_add_v4(op + lc, v0, v1, v2, v3);
            }
        }
        s0 = ns0; d0 = nd0; s1 = ns1; d1 = nd1;
        p ^= 1;
    }
}

extern "C" void kernel_launch(void* const* d_in, const int* in_sizes, int n_in,
                              void* d_out, int out_size) {
    const float* x    = (const float*)d_in[0];
    const int*   eidx = (const int*)d_in[1];   // int32 [2][E]
    const float* ea   = (const float*)d_in[2];
    const float* W    = (const float*)d_in[3];
    const float* b    = (const float*)d_in[4];
    float* out = (float*)d_out;

    const int N = in_sizes[0] / 128;   // 50000
    const int E = in_sizes[2] / 64;    // 800000
    const int ntilesN = (N + 127) / 128;
    const int ntilesE = (E + 15) / 16; // 16-edge tiles

    cudaFuncSetAttribute(node_fused_kernel,
                         cudaFuncAttributeMaxDynamicSharedMemorySize, NODE_SMEM);
    cudaFuncSetAttribute(edge_mma_kernel,
                         cudaFuncAttributeMaxDynamicSharedMemorySize, EDGE_SMEM);

    node_fused_kernel<<<NB_ZERO + ntilesN, 256, NODE_SMEM>>>(x, W, b, out, out_size, N, ntilesN);

    edge_mma_kernel<<<296, 256, EDGE_SMEM>>>(eidx, ea, W, out, E, N, ntilesE);
}